// round 7
// baseline (speedup 1.0000x reference)
#include <cuda_runtime.h>

// ---------------- problem constants ----------------
#define Mdim 512
#define Ndim 1024
#define OUTER 200
#define INNER 20
#define RHO 1.0f
#define XSTEP 1e-3f

// ---------------- kernel config ----------------
#define P 128            // persistent CTAs
#define NR 8             // Ndim / P : x/G rows per CTA (one per warp)
#define MR 4             // Mdim / P : m rows per CTA
#define NTHREADS 256
#define XPT 4            // x elements per thread
#define RPT 2            // r elements per thread
#define TAGSTRIDE 32     // ints per tag slot = 128B line padding

// ---------------- device scratch ----------------
__device__ float g_G[Ndim * Ndim];     // Gram A^T A
__device__ float g_x[2][Ndim];         // parity-buffered raw x
__device__ float g_r[2][Mdim];         // parity-buffered raw r/u
__device__ int   g_tagv[P * TAGSTRIDE];// per-CTA monotonic event tag (128B apart)

// ---------------- exchange primitives ----------------
__device__ __forceinline__ void st_cg_f32(float* p, float v) {
    asm volatile("st.global.cg.f32 [%0], %1;" :: "l"(p), "f"(v) : "memory");
}
__device__ __forceinline__ float4 ld_cg_v4(const float* p) {
    float4 v;
    asm volatile("ld.global.cg.v4.f32 {%0,%1,%2,%3}, [%4];"
                 : "=f"(v.x), "=f"(v.y), "=f"(v.z), "=f"(v.w) : "l"(p) : "memory");
    return v;
}
__device__ __forceinline__ float2 ld_cg_v2(const float* p) {
    float2 v;
    asm volatile("ld.global.cg.v2.f32 {%0,%1}, [%2];"
                 : "=f"(v.x), "=f"(v.y) : "l"(p) : "memory");
    return v;
}
__device__ __forceinline__ void st_release(int* p, int v) {
    asm volatile("st.release.gpu.global.s32 [%0], %1;" :: "l"(p), "r"(v) : "memory");
}
// spin until tag >= evt (tags are monotonic)
__device__ __forceinline__ void wait_tag(const int* p, int evt) {
    int v;
    do {
        asm volatile("ld.acquire.gpu.global.s32 %0, [%1];" : "=r"(v) : "l"(p) : "memory");
    } while (v < evt);
}

// ---------------- init: zero tags each launch (graph-replay safe) ----------------
__global__ void k_init_tags() {
    int t = blockIdx.x * blockDim.x + threadIdx.x;
    if (t < P * TAGSTRIDE) g_tagv[t] = 0;
}

// ---------------- G = A^T A ----------------
__global__ void k_gram(const float* __restrict__ A) {
    int i = blockIdx.x * 16 + threadIdx.x;
    int j = blockIdx.y * 16 + threadIdx.y;
    float a0 = 0.f, a1 = 0.f, a2 = 0.f, a3 = 0.f;
    for (int k = 0; k < Mdim; k += 4) {
        float aj0 = __ldg(&A[(k + 0) * Ndim + j]);
        float aj1 = __ldg(&A[(k + 1) * Ndim + j]);
        float aj2 = __ldg(&A[(k + 2) * Ndim + j]);
        float aj3 = __ldg(&A[(k + 3) * Ndim + j]);
        a0 = fmaf(aj0, __ldg(&A[(k + 0) * Ndim + i]), a0);
        a1 = fmaf(aj1, __ldg(&A[(k + 1) * Ndim + i]), a1);
        a2 = fmaf(aj2, __ldg(&A[(k + 2) * Ndim + i]), a2);
        a3 = fmaf(aj3, __ldg(&A[(k + 3) * Ndim + i]), a3);
    }
    g_G[(size_t)j * Ndim + i] = (a0 + a1) + (a2 + a3);
}

__device__ __forceinline__ float warp_allreduce(float acc) {
#pragma unroll
    for (int off = 16; off; off >>= 1)
        acc += __shfl_xor_sync(0xffffffffu, acc, off);
    return acc;
}

// ---------------- main persistent ADMM kernel ----------------
__global__ void __launch_bounds__(NTHREADS, 1)
k_admm(const float* __restrict__ A, const float* __restrict__ b,
       const float* __restrict__ c, float* __restrict__ out) {
    __shared__ float part[NR][NTHREADS];   // 8 KB partials (bar-protected, single buffer)
    __shared__ float ATs[NR][Mdim];        // 16 KB A^T rows (A cols j0..j0+7)
    __shared__ float rs[Mdim];             // 2 KB r (u at epilogue)

    const int k    = blockIdx.x;
    const int tid  = threadIdx.x;
    const int w    = tid >> 5;
    const int lane = tid & 31;
    const int j0   = k * NR;
    const int i0   = k * MR;

    const int* mytag  = &g_tagv[(tid >> 1) * TAGSTRIDE];  // the ONE producer this thread depends on
    int*       ourtag = &g_tagv[k * TAGSTRIDE];

    // ---- register-resident matrix chunks (iteration-invariant) ----
    float4 Gr[NR];
#pragma unroll
    for (int r = 0; r < NR; r++)
        Gr[r] = *reinterpret_cast<const float4*>(g_G + (size_t)(j0 + r) * Ndim + tid * XPT);
    float4 Arw[MR];
#pragma unroll
    for (int r = 0; r < MR; r++)
        Arw[r] = *reinterpret_cast<const float4*>(A + (size_t)(i0 + r) * Ndim + tid * XPT);

    for (int t = tid; t < NR * Mdim; t += NTHREADS) {
        int i = t >> 3, r = t & 7;
        ATs[r][i] = A[(size_t)i * Ndim + j0 + r];
    }

    // ---- replicated per-warp state (identical on all lanes) ----
    float xr[XPT];
#pragma unroll
    for (int e = 0; e < XPT; e++) xr[e] = 0.f;
    float xval = 0.f;
    const float cval = c[j0 + w];
    float hval = 0.f;
    float sv = 0.f, uv = 0.f, bv = 0.f;
    if (w < MR) bv = b[i0 + w];

    // ---- publish r^1 = b (event 1): data stores, bar, release tag ----
    if (tid < MR) st_cg_f32(&g_r[1][i0 + tid], b[i0 + tid]);
    __syncthreads();
    if (tid == 0) st_release(ourtag, 1);

    for (int o = 0; o < OUTER; o++) {
        const int eo = o * 21 + 1;          // event number of r^{o+1}

        // ---- consume r^{o+1}: 1 tag poll + 1 v2 data load per thread ----
        wait_tag(mytag, eo);
        {
            float2 rv = ld_cg_v2(&g_r[(o + 1) & 1][tid * RPT]);
            rs[tid * RPT]     = rv.x;
            rs[tid * RPT + 1] = rv.y;
        }
        __syncthreads();

        // ---- h = (A^T r)[j0+w] : row-per-warp ----
        {
            const float4* ap = reinterpret_cast<const float4*>(ATs[w]);
            const float4* rp = reinterpret_cast<const float4*>(rs);
            float a0 = 0.f, a1 = 0.f, a2 = 0.f, a3 = 0.f;
#pragma unroll
            for (int q = 0; q < Mdim / 128; q++) {
                float4 a4 = ap[lane + 32 * q], r4 = rp[lane + 32 * q];
                a0 = fmaf(a4.x, r4.x, a0); a1 = fmaf(a4.y, r4.y, a1);
                a2 = fmaf(a4.z, r4.z, a2); a3 = fmaf(a4.w, r4.w, a3);
            }
            hval = warp_allreduce((a0 + a1) + (a2 + a3));
        }

        // ---- inner projected-GD loop ----
        for (int t = 0; t < INNER; t++) {
            const int seq = o * INNER + t;  // consuming x^seq, producing x^{seq+1}
            const int evt = eo + 1 + t;     // event number of x^{seq+1}

            // partials of (G x^seq)
#pragma unroll
            for (int r = 0; r < NR; r++) {
                float a = Gr[r].x * xr[0];
                a = fmaf(Gr[r].y, xr[1], a);
                a = fmaf(Gr[r].z, xr[2], a);
                a = fmaf(Gr[r].w, xr[3], a);
                part[r][tid] = a;
            }
            __syncthreads();                          // bar(a)

            // warp w reduces row w (all lanes), update; lane0 stores data early
            {
                float s = 0.f;
#pragma unroll
                for (int j = 0; j < NTHREADS / 32; j++) s += part[w][lane + 32 * j];
                s = warp_allreduce(s);
                float grad = cval + RHO * (s - hval);
                xval = fmaxf(xval - XSTEP * grad, 0.f);
                if (lane == 0)
                    st_cg_f32(&g_x[(seq + 1) & 1][j0 + w], xval);  // weak data store
            }
            __syncthreads();                          // bar(b): all 8 data stores issued
            if (tid == 0) st_release(ourtag, evt);    // release covers them (h-b via bar)

            // consume x^{seq+1}: 1 tag poll + 1 v4 load
            wait_tag(mytag, evt);
            {
                float4 xv = ld_cg_v4(&g_x[(seq + 1) & 1][tid * XPT]);
                xr[0] = xv.x; xr[1] = xv.y; xr[2] = xv.z; xr[3] = xv.w;
            }
        }

        // ---- Ax partials + s,u update + publish r^{o+2} (or u) ----
#pragma unroll
        for (int r = 0; r < MR; r++) {
            float a = Arw[r].x * xr[0];
            a = fmaf(Arw[r].y, xr[1], a);
            a = fmaf(Arw[r].z, xr[2], a);
            a = fmaf(Arw[r].w, xr[3], a);
            part[r][tid] = a;
        }
        __syncthreads();
        if (w < MR) {
            float s2 = 0.f;
#pragma unroll
            for (int j = 0; j < NTHREADS / 32; j++) s2 += part[w][lane + 32 * j];
            s2 = warp_allreduce(s2);
            float ax = s2;
            sv = fmaxf(ax - bv + uv, 0.f);
            uv = uv + (ax - sv - bv);
            float rv = (o == OUTER - 1) ? uv : (sv + bv - uv);
            if (lane == 0) st_cg_f32(&g_r[(o + 2) & 1][i0 + w], rv);
        }
        __syncthreads();
        if (tid == 0) st_release(ourtag, eo + 21);    // event of r^{o+2} / u
    }

    // ---------------- epilogue ----------------
    // consume u (event OUTER*21 + 1)
    wait_tag(mytag, OUTER * 21 + 1);
    {
        float2 rv = ld_cg_v2(&g_r[(OUTER + 1) & 1][tid * RPT]);
        rs[tid * RPT]     = rv.x;
        rs[tid * RPT + 1] = rv.y;
    }
    __syncthreads();

    // x: thread tid holds x[tid*4..+3]; CTA k emits x[8k..8k+7]
    if ((tid >> 1) == k) {
        int base = (tid & 1) * XPT;
#pragma unroll
        for (int e = 0; e < XPT; e++) out[j0 + base + e] = xr[e];
    }
    if (lane == 0 && w < MR) {
        out[Ndim + i0 + w]            = sv;
        out[Ndim + Mdim + i0 + w]     = uv;
        out[Ndim + 2 * Mdim + i0 + w] = fmaxf(-RHO * uv, 0.f);
    }
    // nu = max(c + rho * A^T u, 0)
    {
        const float4* ap = reinterpret_cast<const float4*>(ATs[w]);
        const float4* up = reinterpret_cast<const float4*>(rs);
        float a0 = 0.f, a1 = 0.f, a2 = 0.f, a3 = 0.f;
#pragma unroll
        for (int q = 0; q < Mdim / 128; q++) {
            float4 a4 = ap[lane + 32 * q], u4 = up[lane + 32 * q];
            a0 = fmaf(a4.x, u4.x, a0); a1 = fmaf(a4.y, u4.y, a1);
            a2 = fmaf(a4.z, u4.z, a2); a3 = fmaf(a4.w, u4.w, a3);
        }
        float s = warp_allreduce((a0 + a1) + (a2 + a3));
        if (lane == 0)
            out[Ndim + 3 * Mdim + j0 + w] = fmaxf(cval + RHO * s, 0.f);
    }
}

// ---------------- launch ----------------
extern "C" void kernel_launch(void* const* d_in, const int* in_sizes, int n_in,
                              void* d_out, int out_size) {
    const float *A = nullptr, *b = nullptr, *c = nullptr;
    for (int i = 0; i < n_in; i++) {
        if (in_sizes[i] == Mdim * Ndim)      A = (const float*)d_in[i];
        else if (in_sizes[i] == Mdim)        b = (const float*)d_in[i];
        else if (in_sizes[i] == Ndim)        c = (const float*)d_in[i];
    }
    (void)out_size;

    k_init_tags<<<(P * TAGSTRIDE + 255) / 256, 256>>>();
    dim3 gb(16, 16), gg(Ndim / 16, Ndim / 16);
    k_gram<<<gg, gb>>>(A);
    k_admm<<<P, NTHREADS>>>(A, b, c, (float*)d_out);
}